// round 1
// baseline (speedup 1.0000x reference)
#include <cuda_runtime.h>
#include <cuda_bf16.h>

#define NS 512
#define EMB 256

// scratch (device globals — no allocation allowed)
__device__ float  g_D[NS * NS];
__device__ float  g_sq[NS];
__device__ double g_loss;
__device__ int    g_count;

// Kernel 1: row squared-norms + zero accumulators
__global__ void init_kernel(const float* __restrict__ E) {
    int i = blockIdx.x;
    int t = threadIdx.x;
    float v = E[i * EMB + t];
    __shared__ float red[EMB];
    red[t] = v * v;
    __syncthreads();
    for (int s = EMB / 2; s > 0; s >>= 1) {
        if (t < s) red[t] += red[t + s];
        __syncthreads();
    }
    if (t == 0) {
        g_sq[i] = red[0];
        if (i == 0) { g_loss = 0.0; g_count = 0; }
    }
}

// Kernel 2: D = -2*E*E^T + sq[i] + sq[j]  (16x16 tiled)
__global__ void dist_kernel(const float* __restrict__ E) {
    __shared__ float As[16][17];
    __shared__ float Bs[16][17];
    int tx = threadIdx.x, ty = threadIdx.y;
    int row = blockIdx.y * 16 + ty;
    int col = blockIdx.x * 16 + tx;
    float acc = 0.0f;
    for (int k0 = 0; k0 < EMB; k0 += 16) {
        As[ty][tx] = E[row * EMB + k0 + tx];
        Bs[ty][tx] = E[(blockIdx.x * 16 + ty) * EMB + k0 + tx];
        __syncthreads();
#pragma unroll
        for (int k = 0; k < 16; k++)
            acc += As[ty][k] * Bs[tx][k];
        __syncthreads();
    }
    g_D[row * NS + col] = -2.0f * acc + g_sq[row] + g_sq[col];
}

// Kernel 3: for each positive pair (i<j, same label), argmax over valid
// negatives of rand_u[i,j,n]; accumulate hinge loss + count.
__global__ void pair_kernel(const float* __restrict__ R,
                            const int* __restrict__ lab) {
    int i = blockIdx.x;
    int t = threadIdx.x;
    int wid = t >> 5, lane = t & 31;

    __shared__ float Drow[NS];
    __shared__ int   labs[NS];
    for (int n = t; n < NS; n += 256) {
        Drow[n] = g_D[i * NS + n];
        labs[n] = lab[n];
    }
    __syncthreads();

    int li = labs[i];
    double wloss = 0.0;
    int    wcount = 0;

    for (int j = i + 1 + wid; j < NS; j += 8) {
        if (labs[j] != li) continue;   // warp-uniform: all lanes agree
        float Dij = Drow[j];
        size_t base = ((size_t)i * NS + (size_t)j) * (size_t)NS;

        float bs = -1.0f;              // scores are in [0,1); -1 marks "none"
        int   bi = 0x7fffffff;
        for (int n = lane; n < NS; n += 32) {
            if (labs[n] != li) {
                float L = Dij - Drow[n] + 3.0f;
                if (L > 0.0f) {
                    float s = R[base + n];
                    if (s > bs) { bs = s; bi = n; }  // strict > keeps first occurrence
                }
            }
        }
        // warp argmax, tie-break toward smaller index (first-occurrence semantics)
        for (int off = 16; off; off >>= 1) {
            float os = __shfl_down_sync(0xffffffffu, bs, off);
            int   oi = __shfl_down_sync(0xffffffffu, bi, off);
            if (os > bs || (os == bs && oi < bi)) { bs = os; bi = oi; }
        }
        if (lane == 0 && bs >= -0.5f) {
            float l = Dij - Drow[bi] + 3.0f;       // > 0 by construction (relu identity)
            wloss += (double)l;
            wcount += 1;
        }
    }
    if (lane == 0 && wcount > 0) {
        atomicAdd(&g_loss, wloss);
        atomicAdd(&g_count, wcount);
    }
}

// Kernel 4: finalize
__global__ void finalize_kernel(float* __restrict__ out, int out_size) {
    if (threadIdx.x == 0) {
        int c = g_count;
        int denom = c > 0 ? c : 1;
        out[0] = (float)(g_loss / (double)denom);
        if (out_size > 1) out[1] = (float)c;
        for (int k = 2; k < out_size; k++) out[k] = 0.0f;
    }
}

extern "C" void kernel_launch(void* const* d_in, const int* in_sizes, int n_in,
                              void* d_out, int out_size) {
    const float* E   = (const float*)d_in[0];   // embeddings [512,256] f32
    const int*   lab = (const int*)d_in[1];     // labels [512] i32
    const float* R   = (const float*)d_in[2];   // rand_u [512,512,512] f32
    float* out = (float*)d_out;

    init_kernel<<<NS, EMB>>>(E);
    dim3 gb(NS / 16, NS / 16), tb(16, 16);
    dist_kernel<<<gb, tb>>>(E);
    pair_kernel<<<NS, 256>>>(R, lab);
    finalize_kernel<<<1, 32>>>(out, out_size);
}

// round 5
// speedup vs baseline: 1.2884x; 1.2884x over previous
#include <cuda_runtime.h>
#include <cuda_bf16.h>

#define NS 512
#define EMB 256

// scratch (device globals — no allocation allowed)
__device__ float  g_G[NS * NS];     // gram matrix E·E^T
__device__ float  g_diag[NS];       // diagonal = squared norms
__device__ double g_loss;
__device__ int    g_count;
__device__ int    g_done;

// Kernel 1: G = E·E^T, 32x32 tiles, 2x2 register blocking.
// Diagonal doubles as the squared-norm vector. Also zeroes accumulators.
__global__ void dot_kernel(const float* __restrict__ E) {
    if (blockIdx.x == 0 && blockIdx.y == 0 && threadIdx.x == 0 && threadIdx.y == 0) {
        g_loss = 0.0; g_count = 0; g_done = 0;
    }
    __shared__ float As[32][34];   // stride 34: float2-aligned, conflict-free
    __shared__ float Bs[32][34];
    const int tx = threadIdx.x;            // 0..15
    const int ty = threadIdx.y;            // 0..15
    const int tid = ty * 16 + tx;
    const int r0 = blockIdx.y * 32;
    const int c0 = blockIdx.x * 32;
    const int lrow = tid >> 3;             // 0..31
    const int lcol = (tid & 7) * 4;        // 0,4,...,28

    float acc00 = 0.f, acc01 = 0.f, acc10 = 0.f, acc11 = 0.f;

    for (int k0 = 0; k0 < EMB; k0 += 32) {
        float4 av = *(const float4*)&E[(r0 + lrow) * EMB + k0 + lcol];
        float4 bv = *(const float4*)&E[(c0 + lrow) * EMB + k0 + lcol];
        As[lrow][lcol + 0] = av.x; As[lrow][lcol + 1] = av.y;
        As[lrow][lcol + 2] = av.z; As[lrow][lcol + 3] = av.w;
        Bs[lrow][lcol + 0] = bv.x; Bs[lrow][lcol + 1] = bv.y;
        Bs[lrow][lcol + 2] = bv.z; Bs[lrow][lcol + 3] = bv.w;
        __syncthreads();
#pragma unroll
        for (int k = 0; k < 32; k += 2) {
            float2 a0 = *(const float2*)&As[ty][k];
            float2 a1 = *(const float2*)&As[ty + 16][k];
            float2 b0 = *(const float2*)&Bs[tx][k];
            float2 b1 = *(const float2*)&Bs[tx + 16][k];
            acc00 += a0.x * b0.x + a0.y * b0.y;
            acc01 += a0.x * b1.x + a0.y * b1.y;
            acc10 += a1.x * b0.x + a1.y * b0.y;
            acc11 += a1.x * b1.x + a1.y * b1.y;
        }
        __syncthreads();
    }

    int r_a = r0 + ty, r_b = r0 + ty + 16;
    int c_a = c0 + tx, c_b = c0 + tx + 16;
    g_G[r_a * NS + c_a] = acc00;
    g_G[r_a * NS + c_b] = acc01;
    g_G[r_b * NS + c_a] = acc10;
    g_G[r_b * NS + c_b] = acc11;
    if (r_a == c_a) g_diag[r_a] = acc00;
    if (r_a == c_b) g_diag[r_a] = acc01;
    if (r_b == c_a) g_diag[r_b] = acc10;
    if (r_b == c_b) g_diag[r_b] = acc11;
}

// Kernel 2: per-anchor block. Builds D row from G + diag, does the
// random-hard-negative argmax per positive pair, accumulates loss/count,
// and the LAST block to finish writes the final output (fused finalize).
__global__ void pair_kernel(const float* __restrict__ R,
                            const int* __restrict__ lab,
                            float* __restrict__ out, int out_size) {
    const int i = blockIdx.x;
    const int t = threadIdx.x;
    const int wid = t >> 5, lane = t & 31;

    __shared__ float Drow[NS];
    __shared__ int   labs[NS];
    float di = g_diag[i];
    for (int n = t; n < NS; n += 256) {
        Drow[n] = di + g_diag[n] - 2.0f * g_G[i * NS + n];
        labs[n] = lab[n];
    }
    __syncthreads();

    const int li = labs[i];
    double wloss = 0.0;
    int    wcount = 0;

    for (int j = i + 1 + wid; j < NS; j += 8) {
        if (labs[j] != li) continue;      // warp-uniform
        float Dij = Drow[j];
        size_t base = ((size_t)i * NS + (size_t)j) * (size_t)NS;

        float bs = -1.0f;                 // scores in [0,1); -1 = none
        int   bi = 0x7fffffff;
#pragma unroll 4
        for (int n = lane; n < NS; n += 32) {
            if (labs[n] != li) {
                float L = Dij - Drow[n] + 3.0f;
                if (L > 0.0f) {
                    float s = R[base + n];
                    if (s > bs) { bs = s; bi = n; }   // strict >: first occurrence
                }
            }
        }
        for (int off = 16; off; off >>= 1) {
            float os = __shfl_down_sync(0xffffffffu, bs, off);
            int   oi = __shfl_down_sync(0xffffffffu, bi, off);
            if (os > bs || (os == bs && oi < bi)) { bs = os; bi = oi; }
        }
        if (lane == 0 && bs >= -0.5f) {
            wloss += (double)(Dij - Drow[bi] + 3.0f);
            wcount += 1;
        }
    }
    if (lane == 0 && wcount > 0) {
        atomicAdd(&g_loss, wloss);
        atomicAdd(&g_count, wcount);
    }
    __syncthreads();

    // fused finalize: last block to arrive writes the output
    if (t == 0) {
        __threadfence();
        int prev = atomicAdd(&g_done, 1);
        if (prev == (int)gridDim.x - 1) {
            double l = atomicAdd(&g_loss, 0.0);   // acquire-safe reads
            int    c = atomicAdd(&g_count, 0);
            int denom = c > 0 ? c : 1;
            out[0] = (float)(l / (double)denom);
            if (out_size > 1) out[1] = (float)c;
            for (int k = 2; k < out_size; k++) out[k] = 0.0f;
        }
    }
}

extern "C" void kernel_launch(void* const* d_in, const int* in_sizes, int n_in,
                              void* d_out, int out_size) {
    const float* E   = (const float*)d_in[0];   // embeddings [512,256] f32
    const int*   lab = (const int*)d_in[1];     // labels [512] i32
    const float* R   = (const float*)d_in[2];   // rand_u [512,512,512] f32
    float* out = (float*)d_out;

    dim3 gb(NS / 32, NS / 32), tb(16, 16);
    dot_kernel<<<gb, tb>>>(E);
    pair_kernel<<<NS, 256>>>(R, lab, out, out_size);
}

// round 9
// speedup vs baseline: 2.4353x; 1.8901x over previous
#include <cuda_runtime.h>
#include <cuda_bf16.h>
#include <float.h>

#define NS 512
#define EMB 256

// scratch (device globals — no allocation allowed)
__device__ float  g_G[NS * NS];     // gram matrix E·E^T
__device__ float  g_diag[NS];       // diagonal = squared norms
__device__ double g_loss;
__device__ int    g_count;
__device__ int    g_done;

// Kernel 1: G = E·E^T, 32x32 tiles, 2x2 register blocking.
__global__ void dot_kernel(const float* __restrict__ E) {
    if (blockIdx.x == 0 && blockIdx.y == 0 && threadIdx.x == 0 && threadIdx.y == 0) {
        g_loss = 0.0; g_count = 0; g_done = 0;
    }
    __shared__ float As[32][34];
    __shared__ float Bs[32][34];
    const int tx = threadIdx.x;            // 0..15
    const int ty = threadIdx.y;            // 0..15
    const int tid = ty * 16 + tx;
    const int r0 = blockIdx.y * 32;
    const int c0 = blockIdx.x * 32;
    const int lrow = tid >> 3;             // 0..31
    const int lcol = (tid & 7) * 4;        // 0,4,...,28

    float acc00 = 0.f, acc01 = 0.f, acc10 = 0.f, acc11 = 0.f;

    for (int k0 = 0; k0 < EMB; k0 += 32) {
        float4 av = *(const float4*)&E[(r0 + lrow) * EMB + k0 + lcol];
        float4 bv = *(const float4*)&E[(c0 + lrow) * EMB + k0 + lcol];
        As[lrow][lcol + 0] = av.x; As[lrow][lcol + 1] = av.y;
        As[lrow][lcol + 2] = av.z; As[lrow][lcol + 3] = av.w;
        Bs[lrow][lcol + 0] = bv.x; Bs[lrow][lcol + 1] = bv.y;
        Bs[lrow][lcol + 2] = bv.z; Bs[lrow][lcol + 3] = bv.w;
        __syncthreads();
#pragma unroll
        for (int k = 0; k < 32; k += 2) {
            float2 a0 = *(const float2*)&As[ty][k];
            float2 a1 = *(const float2*)&As[ty + 16][k];
            float2 b0 = *(const float2*)&Bs[tx][k];
            float2 b1 = *(const float2*)&Bs[tx + 16][k];
            acc00 += a0.x * b0.x + a0.y * b0.y;
            acc01 += a0.x * b1.x + a0.y * b1.y;
            acc10 += a1.x * b0.x + a1.y * b0.y;
            acc11 += a1.x * b1.x + a1.y * b1.y;
        }
        __syncthreads();
    }

    int r_a = r0 + ty, r_b = r0 + ty + 16;
    int c_a = c0 + tx, c_b = c0 + tx + 16;
    g_G[r_a * NS + c_a] = acc00;
    g_G[r_a * NS + c_b] = acc01;
    g_G[r_b * NS + c_a] = acc10;
    g_G[r_b * NS + c_b] = acc11;
    if (r_a == c_a) g_diag[r_a] = acc00;
    if (r_a == c_b) g_diag[r_a] = acc01;
    if (r_b == c_a) g_diag[r_b] = acc10;
    if (r_b == c_b) g_diag[r_b] = acc11;
}

// Kernel 2: per-anchor block. Random-hard-negative argmax per positive
// pair with full-row float4 prefetch (MLP=4 wide loads) and a precomputed
// smem threshold array so the hot loop is register-only compares.
__global__ void pair_kernel(const float* __restrict__ R,
                            const int* __restrict__ lab,
                            float* __restrict__ out, int out_size) {
    const int i = blockIdx.x;
    const int t = threadIdx.x;
    const int wid = t >> 5, lane = t & 31;

    __shared__ float Drow[NS];
    __shared__ float adj[NS];     // labs[n]==li ? +INF : Drow[n]-MARGIN
    __shared__ int   labs[NS];
    const float di = g_diag[i];
    const int   li = lab[i];
    for (int n = t; n < NS; n += 256) {
        int   ln = lab[n];
        float D  = di + g_diag[n] - 2.0f * g_G[i * NS + n];
        Drow[n] = D;
        labs[n] = ln;
        adj[n]  = (ln == li) ? FLT_MAX : (D - 3.0f);
    }
    __syncthreads();

    const float4* __restrict__ adj4 = (const float4*)adj;
    // threshold values are loop-invariant per block: hoist out of the j loop
    const float4 a0 = adj4[lane];
    const float4 a1 = adj4[lane + 32];
    const float4 a2 = adj4[lane + 64];
    const float4 a3 = adj4[lane + 96];
    const int nb0 = lane * 4;

    double wloss = 0.0;
    int    wcount = 0;

    for (int j = i + 1 + wid; j < NS; j += 8) {
        if (labs[j] != li) continue;       // warp-uniform
        const float Dij = Drow[j];
        const float4* __restrict__ R4 =
            (const float4*)(R + ((size_t)i * NS + (size_t)j) * (size_t)NS);

        // 4 independent LDG.128 per lane — full row prefetched, MLP=4
        float4 r0 = R4[lane];
        float4 r1 = R4[lane + 32];
        float4 r2 = R4[lane + 64];
        float4 r3 = R4[lane + 96];

        float bs = -1.0f;                  // scores in [0,1); -1 = none
        int   bi = 0x7fffffff;
        // n ascending within lane + strict > ⇒ first-occurrence kept
        if (Dij > a0.x && r0.x > bs) { bs = r0.x; bi = nb0 + 0; }
        if (Dij > a0.y && r0.y > bs) { bs = r0.y; bi = nb0 + 1; }
        if (Dij > a0.z && r0.z > bs) { bs = r0.z; bi = nb0 + 2; }
        if (Dij > a0.w && r0.w > bs) { bs = r0.w; bi = nb0 + 3; }
        if (Dij > a1.x && r1.x > bs) { bs = r1.x; bi = nb0 + 128; }
        if (Dij > a1.y && r1.y > bs) { bs = r1.y; bi = nb0 + 129; }
        if (Dij > a1.z && r1.z > bs) { bs = r1.z; bi = nb0 + 130; }
        if (Dij > a1.w && r1.w > bs) { bs = r1.w; bi = nb0 + 131; }
        if (Dij > a2.x && r2.x > bs) { bs = r2.x; bi = nb0 + 256; }
        if (Dij > a2.y && r2.y > bs) { bs = r2.y; bi = nb0 + 257; }
        if (Dij > a2.z && r2.z > bs) { bs = r2.z; bi = nb0 + 258; }
        if (Dij > a2.w && r2.w > bs) { bs = r2.w; bi = nb0 + 259; }
        if (Dij > a3.x && r3.x > bs) { bs = r3.x; bi = nb0 + 384; }
        if (Dij > a3.y && r3.y > bs) { bs = r3.y; bi = nb0 + 385; }
        if (Dij > a3.z && r3.z > bs) { bs = r3.z; bi = nb0 + 386; }
        if (Dij > a3.w && r3.w > bs) { bs = r3.w; bi = nb0 + 387; }

        // warp argmax, tie-break toward smaller index
        for (int off = 16; off; off >>= 1) {
            float os = __shfl_down_sync(0xffffffffu, bs, off);
            int   oi = __shfl_down_sync(0xffffffffu, bi, off);
            if (os > bs || (os == bs && oi < bi)) { bs = os; bi = oi; }
        }
        if (lane == 0 && bs >= -0.5f) {
            wloss += (double)(Dij - Drow[bi] + 3.0f);
            wcount += 1;
        }
    }
    if (lane == 0 && wcount > 0) {
        atomicAdd(&g_loss, wloss);
        atomicAdd(&g_count, wcount);
    }
    __syncthreads();

    // fused finalize: last block to arrive writes the output
    if (t == 0) {
        __threadfence();
        int prev = atomicAdd(&g_done, 1);
        if (prev == (int)gridDim.x - 1) {
            double l = atomicAdd(&g_loss, 0.0);
            int    c = atomicAdd(&g_count, 0);
            int denom = c > 0 ? c : 1;
            out[0] = (float)(l / (double)denom);
            if (out_size > 1) out[1] = (float)c;
            for (int k = 2; k < out_size; k++) out[k] = 0.0f;
        }
    }
}

extern "C" void kernel_launch(void* const* d_in, const int* in_sizes, int n_in,
                              void* d_out, int out_size) {
    const float* E   = (const float*)d_in[0];   // embeddings [512,256] f32
    const int*   lab = (const int*)d_in[1];     // labels [512] i32
    const float* R   = (const float*)d_in[2];   // rand_u [512,512,512] f32
    float* out = (float*)d_out;

    dim3 gb(NS / 32, NS / 32), tb(16, 16);
    dot_kernel<<<gb, tb>>>(E);
    pair_kernel<<<NS, 256>>>(R, lab, out, out_size);
}